// round 14
// baseline (speedup 1.0000x reference)
#include <cuda_runtime.h>
#include <cuda_bf16.h>
#include <cstdint>

// x: (16, 64, 256, 256) fp32 = 16 Mi float4.  posIdx: 64 int32.
// out = posIdx[c] ? relu(x) : x
//
// R14 probe: 512-thread blocks, same MLP=4 pattern (tile = 2048 vec4).
// 2048 | 16384 vec4/channel -> block still single-channel:
//   c = (blockIdx.x >> 3) & 63
// Everything else is the validated R4 config (.cs loads+stores, flat grid).

__global__ void __launch_bounds__(512) partial_relu_kernel(
    const float4* __restrict__ x,
    const int* __restrict__ posIdx,
    float4* __restrict__ out)
{
    const unsigned int base = blockIdx.x * 2048u + threadIdx.x;
    const bool m = posIdx[(blockIdx.x >> 3) & 63u] != 0;   // uniform per block

    float4 v0 = __ldcs(&x[base]);
    float4 v1 = __ldcs(&x[base + 512u]);
    float4 v2 = __ldcs(&x[base + 1024u]);
    float4 v3 = __ldcs(&x[base + 1536u]);

    if (m) {
        v0.x = fmaxf(v0.x, 0.0f); v0.y = fmaxf(v0.y, 0.0f);
        v0.z = fmaxf(v0.z, 0.0f); v0.w = fmaxf(v0.w, 0.0f);
        v1.x = fmaxf(v1.x, 0.0f); v1.y = fmaxf(v1.y, 0.0f);
        v1.z = fmaxf(v1.z, 0.0f); v1.w = fmaxf(v1.w, 0.0f);
        v2.x = fmaxf(v2.x, 0.0f); v2.y = fmaxf(v2.y, 0.0f);
        v2.z = fmaxf(v2.z, 0.0f); v2.w = fmaxf(v2.w, 0.0f);
        v3.x = fmaxf(v3.x, 0.0f); v3.y = fmaxf(v3.y, 0.0f);
        v3.z = fmaxf(v3.z, 0.0f); v3.w = fmaxf(v3.w, 0.0f);
    }

    __stcs(&out[base],         v0);
    __stcs(&out[base + 512u],  v1);
    __stcs(&out[base + 1024u], v2);
    __stcs(&out[base + 1536u], v3);
}

extern "C" void kernel_launch(void* const* d_in, const int* in_sizes, int n_in,
                              void* d_out, int out_size)
{
    const float4* x = (const float4*)d_in[0];
    const int* posIdx = (const int*)d_in[1];
    float4* out = (float4*)d_out;

    // 16777216 vec4 / 2048 per block = 8192 blocks
    partial_relu_kernel<<<8192, 512>>>(x, posIdx, out);
}